// round 14
// baseline (speedup 1.0000x reference)
#include <cuda_runtime.h>

#define N_GAUSS 4096
#define N_PTS 32768
#define NCELL 4096               /* 16^3 grid, cell side 0.5 over [-4,4], x-fastest */

typedef unsigned long long u64;

// fixed-point scale 2^45
#define FPSCALE 35184372088832.0
#define FPINV   (1.0 / 35184372088832.0)

__device__ float4 g_prm[N_GAUSS * 7];          // per-gaussian params (see prep)
__device__ int    g_off[NCELL];                // cell start in sorted order
__device__ int    g_ocnt[NCELL];               // cell count
__device__ int    g_perm[N_PTS];               // sorted slot -> original point
__device__ float4 g_spts[N_PTS];               // sorted NEGATED points
__device__ u64    g_acc[2 * N_PTS];            // fixed-point sums (zero-init; finalize re-zeros)

__device__ __forceinline__ float ex2f(float x) {
    float y; asm("ex2.approx.ftz.f32 %0, %1;" : "=f"(y) : "f"(x)); return y;
}
__device__ __forceinline__ float rsqf(float x) {
    float y; asm("rsqrt.approx.ftz.f32 %0, %1;" : "=f"(y) : "f"(x)); return y;
}
__device__ __forceinline__ int cellof(float v) {
    return min(15, max(0, (int)floorf((v + 4.f) * 2.f)));
}

// ---------------------------------------------------------------------------
// K1: per-gaussian preprocessing.
//  g_prm[g*7+0] = (gx, gy, gz, T)            T = 230*smax^2 (exact-zero cull radius^2)
//  [1] = (kP0, kP1, kP2, kP3)   precision * -0.5*log2(e), off-diagonals doubled
//  [2] = (kP4, kP5, op, c0)
//  [3..6] = c1..c15 (SH coefficients with basis constants folded), last slot pad
// n2 >= T  =>  exp(-0.5*maha) == +0.0f exactly (in the fp32 reference too).
// ---------------------------------------------------------------------------
__global__ void prep_kernel(const float* __restrict__ xyz,
                            const float* __restrict__ sh_dc,
                            const float* __restrict__ sh_rest,
                            const float* __restrict__ scaling,
                            const float* __restrict__ rotation,
                            const float* __restrict__ opacity) {
    int g = blockIdx.x * blockDim.x + threadIdx.x;
    if (g >= N_GAUSS) return;

    float qr = rotation[g*4+0], qx = rotation[g*4+1];
    float qy = rotation[g*4+2], qz = rotation[g*4+3];
    float qn = rsqrtf(qr*qr + qx*qx + qy*qy + qz*qz);
    qr *= qn; qx *= qn; qy *= qn; qz *= qn;

    float R00 = 1.f - 2.f*(qy*qy + qz*qz), R01 = 2.f*(qx*qy - qr*qz), R02 = 2.f*(qx*qz + qr*qy);
    float R10 = 2.f*(qx*qy + qr*qz), R11 = 1.f - 2.f*(qx*qx + qz*qz), R12 = 2.f*(qy*qz - qr*qx);
    float R20 = 2.f*(qx*qz - qr*qy), R21 = 2.f*(qy*qz + qr*qx), R22 = 1.f - 2.f*(qx*qx + qy*qy);

    float s0 = expf(scaling[g*3+0]);
    float s1 = expf(scaling[g*3+1]);
    float s2 = expf(scaling[g*3+2]);
    float iv0 = 1.f/(s0*s0), iv1 = 1.f/(s1*s1), iv2 = 1.f/(s2*s2);
    float smax = fmaxf(s0, fmaxf(s1, s2));
    float T = 230.f * smax * smax;

    float Pxx = iv0*R00*R00 + iv1*R01*R01 + iv2*R02*R02;
    float Pyy = iv0*R10*R10 + iv1*R11*R11 + iv2*R12*R12;
    float Pzz = iv0*R20*R20 + iv1*R21*R21 + iv2*R22*R22;
    float Pxy = iv0*R00*R10 + iv1*R01*R11 + iv2*R02*R12;
    float Pxz = iv0*R00*R20 + iv1*R01*R21 + iv2*R02*R22;
    float Pyz = iv0*R10*R20 + iv1*R11*R21 + iv2*R12*R22;

    const float kk = -0.7213475204444817f;  // -0.5 * log2(e)
    float op = 1.f / (1.f + expf(-opacity[g]));

    const float C0 = 0.28209479177387814f;
    const float C1 = 0.4886025119029199f;
    const float* sr = sh_rest + g*15;
    float c0  =  C0 * sh_dc[g];
    float c1  = -C1 * sr[0];
    float c2  =  C1 * sr[1];
    float c3  = -C1 * sr[2];
    float c4  =  1.0925484305920792f  * sr[3];
    float c5  = -1.0925484305920792f  * sr[4];
    float c6  =  0.31539156525252005f * sr[5];
    float c7  = -1.0925484305920792f  * sr[6];
    float c8  =  0.5462742152960396f  * sr[7];
    float c9  = -0.5900435899266435f  * sr[8];
    float c10 =  2.890611442640554f   * sr[9];
    float c11 = -0.4570457994644658f  * sr[10];
    float c12 =  0.3731763325901154f  * sr[11];
    float c13 = -0.4570457994644658f  * sr[12];
    float c14 =  1.445305721320277f   * sr[13];
    float c15 = -0.5900435899266435f  * sr[14];

    float4* o = &g_prm[g*7];
    o[0] = make_float4(xyz[g*3+0], xyz[g*3+1], xyz[g*3+2], T);
    o[1] = make_float4(kk*Pxx, kk*Pyy, kk*Pzz, 2.f*kk*Pxy);
    o[2] = make_float4(2.f*kk*Pxz, 2.f*kk*Pyz, op, c0);
    o[3] = make_float4(c1, c2, c3, c4);
    o[4] = make_float4(c5, c6, c7, c8);
    o[5] = make_float4(c9, c10, c11, c12);
    o[6] = make_float4(c13, c14, c15, 0.f);
}

// ---------------------------------------------------------------------------
// K2: fused count + scan + scatter, single CTA (one global-sync-free sort).
// Linear cell id (x fastest): c = ix + 16*iy + 256*iz, so an x-run of cells
// with fixed (iy,iz) is CONTIGUOUS in the sorted point array.
// Within-cell order from SMEM atomics is nondeterministic but harmless:
// per-point results are computed identically whichever slot/lane holds the
// point, excluded terms are exactly +0.0, and the u64 accumulation in K3 is
// order-invariant -> outputs are permutation-invariant.
// ---------------------------------------------------------------------------
__global__ void __launch_bounds__(1024) sort_kernel(const float* __restrict__ pts) {
    __shared__ int scnt[NCELL];     // counts, then reused as cursors
    __shared__ int ps[1024];
    int t = threadIdx.x;

#pragma unroll
    for (int k = 0; k < 4; ++k) scnt[t*4+k] = 0;
    __syncthreads();

    int cids[32];
#pragma unroll 4
    for (int k = 0; k < 32; ++k) {
        int i = t + k*1024;
        int c = cellof(pts[i*3+0]) | (cellof(pts[i*3+1]) << 4) | (cellof(pts[i*3+2]) << 8);
        cids[k] = c;
        atomicAdd(&scnt[c], 1);
    }
    __syncthreads();

    // exclusive scan over 4096 cells (4 per thread)
    int l0 = scnt[t*4+0], l1 = scnt[t*4+1], l2 = scnt[t*4+2], l3 = scnt[t*4+3];
    int s = l0 + l1 + l2 + l3;
    ps[t] = s; __syncthreads();
    for (int off = 1; off < 1024; off <<= 1) {
        int v = (t >= off) ? ps[t - off] : 0;
        __syncthreads();
        ps[t] += v;
        __syncthreads();
    }
    int run = ps[t] - s;
    g_off[t*4+0] = run; g_ocnt[t*4+0] = l0;
    int r1 = run + l0;
    g_off[t*4+1] = r1;  g_ocnt[t*4+1] = l1;
    int r2 = r1 + l1;
    g_off[t*4+2] = r2;  g_ocnt[t*4+2] = l2;
    int r3 = r2 + l2;
    g_off[t*4+3] = r3;  g_ocnt[t*4+3] = l3;
    __syncthreads();
    scnt[t*4+0] = run; scnt[t*4+1] = r1; scnt[t*4+2] = r2; scnt[t*4+3] = r3;
    __syncthreads();

#pragma unroll 4
    for (int k = 0; k < 32; ++k) {
        int i = t + k*1024;
        int slot = atomicAdd(&scnt[cids[k]], 1);
        g_perm[slot] = i;
        g_spts[slot] = make_float4(-pts[i*3+0], -pts[i*3+1], -pts[i*3+2], 0.f);
    }
}

// ---------------------------------------------------------------------------
// K3: gaussian-centric main. One WARP per gaussian; params live in registers.
// Warp scans only grid rows within reach (border-aware row cull), streams the
// contiguous x-run of sorted points (lane = point, coalesced), and for lanes
// with n2 < T adds fixed-point (2^-45) u64 terms atomically. Integer adds are
// associative -> bit-deterministic output for any arrival order.
// ---------------------------------------------------------------------------
__global__ void __launch_bounds__(128) main_kernel() {
    int warp = blockIdx.x * 4 + (threadIdx.x >> 5);   // gaussian id
    int lane = threadIdx.x & 31;

    const float4* P = &g_prm[warp*7];
    float4 a0 = __ldg(&P[0]);
    float4 a1 = __ldg(&P[1]);
    float4 a2 = __ldg(&P[2]);
    float4 a3 = __ldg(&P[3]);
    float4 a4 = __ldg(&P[4]);
    float4 a5 = __ldg(&P[5]);
    float4 a6 = __ldg(&P[6]);
    float gx = a0.x, gy = a0.y, gz = a0.z, T = a0.w;
    float R = sqrtf(T);

    int xlo = cellof(gx - R), xhi = cellof(gx + R);
    int ylo = cellof(gy - R), yhi = cellof(gy + R);
    int zlo = cellof(gz - R), zhi = cellof(gz + R);

    for (int iz = zlo; iz <= zhi; ++iz) {
        // border-aware z distance to row (border cells hold clamped outliers)
        float lz = (iz == 0)  ? -1e30f : iz*0.5f - 4.f;
        float hz = (iz == 15) ?  1e30f : iz*0.5f - 3.5f;
        float dz = fmaxf(0.f, fmaxf(lz - gz, gz - hz));
        for (int iy = ylo; iy <= yhi; ++iy) {
            float ly = (iy == 0)  ? -1e30f : iy*0.5f - 4.f;
            float hy = (iy == 15) ?  1e30f : iy*0.5f - 3.5f;
            float dy = fmaxf(0.f, fmaxf(ly - gy, gy - hy));
            if (dy*dy + dz*dz >= T) continue;     // row cannot contain a hit

            int cbase = (iy << 4) | (iz << 8);
            int cs = cbase + xlo, ce = cbase + xhi;
            int start = g_off[cs];
            int end   = g_off[ce] + g_ocnt[ce];

            for (int base = start; base < end; base += 32) {
                int i = base + lane;
                bool valid = i < end;
                float4 p = g_spts[valid ? i : start];    // negated point
                float ex = gx + p.x, ey = gy + p.y, ez = gz + p.z;  // g - pt
                float exx = ex*ex, eyy = ey*ey, ezz = ez*ez;
                float n2 = exx + eyy + ezz;
                bool act = valid && (n2 < T);
                if (!__ballot_sync(0xFFFFFFFFu, act)) continue;

                float pxy = ex*ey, pxz = ex*ez, pyz = ey*ez;
                // exponent (precision pre-scaled by -0.5*log2e, off-diag doubled)
                float m = exx*a1.x;
                m = fmaf(eyy, a1.y, m);
                m = fmaf(ezz, a1.z, m);
                m = fmaf(pxy, a1.w, m);
                m = fmaf(pxz, a2.x, m);
                m = fmaf(pyz, a2.y, m);
                float w = a2.z * ex2f(m);            // op * exp(-0.5*maha)

                // SH in e-space, Horner in rinv (validated R3-R7)
                float t6  = fmaf(3.f, ezz, -n2);
                float uq  = exx - eyy;
                float t9  = fmaf(3.f, exx, -eyy);
                float w5  = fmaf(5.f, ezz, -n2);
                float t12 = fmaf(-2.f, n2, w5);
                float t15 = fmaf(-3.f, ezz, uq);
                float S1 = fmaf(ex, a3.z, fmaf(ez, a3.y, ey*a3.x));
                float S2 = fmaf(uq, a4.w,
                           fmaf(pxz, a4.z,
                           fmaf(t6, a4.y,
                           fmaf(pyz, a4.x, pxy*a3.w))));
                float S3 = fmaf(ey*t9, a5.x,
                           fmaf(pxy*ez, a5.y,
                           fmaf(ey*w5, a5.z,
                           fmaf(ez*t12, a5.w,
                           fmaf(ex*w5, a6.x,
                           fmaf(ez*uq, a6.y, (ex*t15)*a6.z))))));
                float r = rsqf(n2);
                float res = fmaf(r, S3, S2);
                res = fmaf(r, res, S1);
                res = fmaf(r, res, a2.w);
                float mag = fmaxf(res, 0.f);

                if (act) {
                    u64 qw = __double2ull_rn((double)w * FPSCALE);
                    u64 qs = __double2ull_rn((double)(w * mag) * FPSCALE);
                    atomicAdd(&g_acc[i], qw);
                    atomicAdd(&g_acc[N_PTS + i], qs);
                }
            }
        }
    }
}

// ---------------------------------------------------------------------------
// K4: convert fixed-point sums to float, un-permute, and re-zero state for
// the next (graph-replayed) call.
// ---------------------------------------------------------------------------
__global__ void finalize_kernel(float* __restrict__ out) {
    int slot = blockIdx.x * blockDim.x + threadIdx.x;
    if (slot >= N_PTS) return;
    u64 aw = g_acc[slot];
    u64 as = g_acc[N_PTS + slot];
    int o = g_perm[slot];
    out[o]         = (float)((double)aw * FPINV);
    out[N_PTS + o] = (float)((double)as * FPINV);
    g_acc[slot] = 0ULL;
    g_acc[N_PTS + slot] = 0ULL;
}

extern "C" void kernel_launch(void* const* d_in, const int* in_sizes, int n_in,
                              void* d_out, int out_size) {
    const float* pts      = (const float*)d_in[0];  // network_pts
    // d_in[1] network_view, d_in[2] network_tx: unused by the reference math
    const float* xyz      = (const float*)d_in[3];
    const float* sh_dc    = (const float*)d_in[4];
    const float* sh_rest  = (const float*)d_in[5];
    const float* scaling  = (const float*)d_in[6];
    const float* rotation = (const float*)d_in[7];
    const float* opacity  = (const float*)d_in[8];

    prep_kernel<<<N_GAUSS/256, 256>>>(xyz, sh_dc, sh_rest, scaling, rotation, opacity);
    sort_kernel<<<1, 1024>>>(pts);
    main_kernel<<<N_GAUSS/4, 128>>>();
    finalize_kernel<<<N_PTS/256, 256>>>((float*)d_out);
}

// round 15
// speedup vs baseline: 1.0898x; 1.0898x over previous
#include <cuda_runtime.h>

#define N_GAUSS 4096
#define N_PTS 32768
#define NSPLIT 8
#define NBLK 128                 /* gaussian blocks of 32 (sorted order) */
#define BPS (NBLK / NSPLIT)      /* 16 blocks per split */
#define U2G 14                   /* ulonglong2 per gaussian (28 dup float2 slots) */
#define NCELL 4096               /* 16^3 Morton grid, cell 0.5 over [-4,4] */
#define NGRP 512                 /* groups of 64 sorted points (one warp each) */

typedef unsigned long long u64;

__device__ ulonglong2 g_prm2[N_GAUSS * U2G];   // dup params, SORTED gaussian order
__device__ float4 g_blk[NBLK * 2];             // per-block negated AABB + maxT
__device__ float  g_partial[NSPLIT * 2 * N_PTS];
__device__ int    g_perm[N_PTS];               // sorted slot -> original point
__device__ int    g_gperm[N_GAUSS];            // sorted slot -> original gaussian
__device__ float4 g_spts[N_PTS];               // sorted NEGATED points

__device__ __forceinline__ float ex2f(float x) {
    float y; asm("ex2.approx.ftz.f32 %0, %1;" : "=f"(y) : "f"(x)); return y;
}
__device__ __forceinline__ float rsqf(float x) {
    float y; asm("rsqrt.approx.ftz.f32 %0, %1;" : "=f"(y) : "f"(x)); return y;
}
__device__ __forceinline__ u64 f2fma(u64 a, u64 b, u64 c) {
    u64 d; asm("fma.rn.f32x2 %0, %1, %2, %3;" : "=l"(d) : "l"(a), "l"(b), "l"(c)); return d;
}
__device__ __forceinline__ u64 f2mul(u64 a, u64 b) {
    u64 d; asm("mul.rn.f32x2 %0, %1, %2;" : "=l"(d) : "l"(a), "l"(b)); return d;
}
__device__ __forceinline__ u64 f2add(u64 a, u64 b) {
    u64 d; asm("add.rn.f32x2 %0, %1, %2;" : "=l"(d) : "l"(a), "l"(b)); return d;
}
__device__ __forceinline__ u64 f2pack(float lo, float hi) {
    u64 d; asm("mov.b64 %0, {%1, %2};" : "=l"(d) : "f"(lo), "f"(hi)); return d;
}
__device__ __forceinline__ void f2unpack(u64 v, float& lo, float& hi) {
    asm("mov.b64 {%0, %1}, %2;" : "=f"(lo), "=f"(hi) : "l"(v));
}
__device__ __forceinline__ u64 f2relu(u64 v) {
    unsigned lo = (unsigned)v, hi = (unsigned)(v >> 32);
    lo &= ~(unsigned)(((int)lo) >> 31);
    hi &= ~(unsigned)(((int)hi) >> 31);
    return ((u64)hi << 32) | lo;
}
__device__ __forceinline__ int cellof(float v) {
    return min(15, max(0, (int)floorf((v + 4.f) * 2.f)));
}
__device__ __forceinline__ int mort3(int ix, int iy, int iz) {
    int c = 0;
#pragma unroll
    for (int b = 0; b < 4; ++b)
        c |= (((ix >> b) & 1) << (3*b)) | (((iy >> b) & 1) << (3*b + 1))
           | (((iz >> b) & 1) << (3*b + 2));
    return c;
}

// ---------------------------------------------------------------------------
// K1: one CTA does BOTH sorts.
//  Phase A: Morton counting-sort of the 32768 points (atomic within-cell order
//   is nondeterministic but provably harmless: every point's nonzero term set
//   is evaluated in fixed sorted-gaussian order regardless of slot/warp, all
//   other terms are exactly +0.0, accumulators never hold -0.0).
//  Phase B: BITONIC sort of the 4096 gaussians on unique keys
//   (morton<<12 | idx) — fully deterministic order.
// ---------------------------------------------------------------------------
__global__ void __launch_bounds__(1024) sort_all_kernel(const float* __restrict__ pts,
                                                        const float* __restrict__ xyz) {
    __shared__ int scnt[NCELL];    // counts -> cursors -> bitonic keys
    __shared__ int ps[1024];
    int t = threadIdx.x;

#pragma unroll
    for (int k = 0; k < 4; ++k) scnt[t*4+k] = 0;
    __syncthreads();

    int cids[32];
#pragma unroll 4
    for (int k = 0; k < 32; ++k) {
        int i = t + k*1024;
        int c = mort3(cellof(pts[i*3+0]), cellof(pts[i*3+1]), cellof(pts[i*3+2]));
        cids[k] = c;
        atomicAdd(&scnt[c], 1);
    }
    __syncthreads();

    int l0 = scnt[t*4+0], l1 = scnt[t*4+1], l2 = scnt[t*4+2], l3 = scnt[t*4+3];
    int s = l0 + l1 + l2 + l3;
    ps[t] = s; __syncthreads();
    for (int off = 1; off < 1024; off <<= 1) {
        int v = (t >= off) ? ps[t - off] : 0;
        __syncthreads();
        ps[t] += v;
        __syncthreads();
    }
    int run = ps[t] - s;
    scnt[t*4+0] = run;
    scnt[t*4+1] = run + l0;
    scnt[t*4+2] = run + l0 + l1;
    scnt[t*4+3] = run + l0 + l1 + l2;
    __syncthreads();

#pragma unroll 4
    for (int k = 0; k < 32; ++k) {
        int i = t + k*1024;
        int slot = atomicAdd(&scnt[cids[k]], 1);
        g_perm[slot] = i;
        g_spts[slot] = make_float4(-pts[i*3+0], -pts[i*3+1], -pts[i*3+2], 0.f);
    }
    __syncthreads();

    // ---- Phase B: gaussian bitonic sort (keys reuse scnt) ----
#pragma unroll
    for (int k = 0; k < 4; ++k) {
        int i = t + k*1024;
        int c = mort3(cellof(xyz[i*3+0]), cellof(xyz[i*3+1]), cellof(xyz[i*3+2]));
        scnt[i] = (c << 12) | i;           // unique keys -> deterministic order
    }
    __syncthreads();

    for (int kk = 2; kk <= N_GAUSS; kk <<= 1) {
        for (int j = kk >> 1; j > 0; j >>= 1) {
#pragma unroll
            for (int m = 0; m < 4; ++m) {
                int i = t + m*1024;
                int l = i ^ j;
                if (l > i) {
                    int a = scnt[i], b = scnt[l];
                    bool up = ((i & kk) == 0);
                    if ((a > b) == up) { scnt[i] = b; scnt[l] = a; }
                }
            }
            __syncthreads();
        }
    }

#pragma unroll
    for (int k = 0; k < 4; ++k) {
        int i = t + k*1024;
        g_gperm[i] = scnt[i] & 0xFFF;
    }
}

// ---------------------------------------------------------------------------
// K2: per-gaussian preprocessing into SORTED order (dup f32x2 layout) +
// per-block (32 sorted gaussians = 1 warp) negated AABB + maxT via shuffles.
//  dup slots: 0:gx 1:gy 2:gz 3:T 4..9:P0..P5 10:op 11:c0 12..27:c1..c15
//  T = 230*smax^2: n2 >= T  =>  exp(-0.5*maha) == +0.0f exactly (reference too).
// ---------------------------------------------------------------------------
__global__ void __launch_bounds__(128) prep_kernel(const float* __restrict__ xyz,
                            const float* __restrict__ sh_dc,
                            const float* __restrict__ sh_rest,
                            const float* __restrict__ scaling,
                            const float* __restrict__ rotation,
                            const float* __restrict__ opacity) {
    int g = blockIdx.x * 128 + threadIdx.x;      // sorted slot
    int og = g_gperm[g];                          // original gaussian
    int lane = threadIdx.x & 31;

    float qr = rotation[og*4+0], qx = rotation[og*4+1];
    float qy = rotation[og*4+2], qz = rotation[og*4+3];
    float qn = rsqrtf(qr*qr + qx*qx + qy*qy + qz*qz);
    qr *= qn; qx *= qn; qy *= qn; qz *= qn;

    float R00 = 1.f - 2.f*(qy*qy + qz*qz), R01 = 2.f*(qx*qy - qr*qz), R02 = 2.f*(qx*qz + qr*qy);
    float R10 = 2.f*(qx*qy + qr*qz), R11 = 1.f - 2.f*(qx*qx + qz*qz), R12 = 2.f*(qy*qz - qr*qx);
    float R20 = 2.f*(qx*qz - qr*qy), R21 = 2.f*(qy*qz + qr*qx), R22 = 1.f - 2.f*(qx*qx + qy*qy);

    float s0 = expf(scaling[og*3+0]);
    float s1 = expf(scaling[og*3+1]);
    float s2 = expf(scaling[og*3+2]);
    float iv0 = 1.f/(s0*s0), iv1 = 1.f/(s1*s1), iv2 = 1.f/(s2*s2);
    float smax = fmaxf(s0, fmaxf(s1, s2));
    float T = 230.f * smax * smax;

    float Pxx = iv0*R00*R00 + iv1*R01*R01 + iv2*R02*R02;
    float Pyy = iv0*R10*R10 + iv1*R11*R11 + iv2*R12*R12;
    float Pzz = iv0*R20*R20 + iv1*R21*R21 + iv2*R22*R22;
    float Pxy = iv0*R00*R10 + iv1*R01*R11 + iv2*R02*R12;
    float Pxz = iv0*R00*R20 + iv1*R01*R21 + iv2*R02*R22;
    float Pyz = iv0*R10*R20 + iv1*R11*R21 + iv2*R12*R22;

    const float kk = -0.7213475204444817f;  // -0.5 * log2(e)
    float op = 1.f / (1.f + expf(-opacity[og]));

    const float C0 = 0.28209479177387814f;
    const float C1 = 0.4886025119029199f;
    const float* sr = sh_rest + og*15;
    float c[16];
    c[0]  =  C0 * sh_dc[og];
    c[1]  = -C1 * sr[0];
    c[2]  =  C1 * sr[1];
    c[3]  = -C1 * sr[2];
    c[4]  =  1.0925484305920792f  * sr[3];
    c[5]  = -1.0925484305920792f  * sr[4];
    c[6]  =  0.31539156525252005f * sr[5];
    c[7]  = -1.0925484305920792f  * sr[6];
    c[8]  =  0.5462742152960396f  * sr[7];
    c[9]  = -0.5900435899266435f  * sr[8];
    c[10] =  2.890611442640554f   * sr[9];
    c[11] = -0.4570457994644658f  * sr[10];
    c[12] =  0.3731763325901154f  * sr[11];
    c[13] = -0.4570457994644658f  * sr[12];
    c[14] =  1.445305721320277f   * sr[13];
    c[15] = -0.5900435899266435f  * sr[14];

    float gx = xyz[og*3+0], gy = xyz[og*3+1], gz = xyz[og*3+2];

    float v[28];
    v[0] = gx; v[1] = gy; v[2] = gz; v[3] = T;
    v[4] = kk*Pxx; v[5] = kk*Pyy; v[6] = kk*Pzz;
    v[7] = 2.f*kk*Pxy; v[8] = 2.f*kk*Pxz; v[9] = 2.f*kk*Pyz;
    v[10] = op; v[11] = c[0];
#pragma unroll
    for (int i = 0; i < 15; ++i) v[12+i] = c[1+i];
    v[27] = 0.f;

    float2* o = (float2*)&g_prm2[g * U2G];
#pragma unroll
    for (int i = 0; i < 28; ++i) o[i] = make_float2(v[i], v[i]);

    // block AABB of NEGATED centers + maxT (warp == block of 32 sorted slots)
    float cx = -gx, cy = -gy, cz = -gz;
    float mnx = cx, mxx = cx, mny = cy, mxy = cy, mnz = cz, mxz = cz, mT = T;
#pragma unroll
    for (int o2 = 16; o2; o2 >>= 1) {
        mnx = fminf(mnx, __shfl_xor_sync(0xFFFFFFFFu, mnx, o2));
        mxx = fmaxf(mxx, __shfl_xor_sync(0xFFFFFFFFu, mxx, o2));
        mny = fminf(mny, __shfl_xor_sync(0xFFFFFFFFu, mny, o2));
        mxy = fmaxf(mxy, __shfl_xor_sync(0xFFFFFFFFu, mxy, o2));
        mnz = fminf(mnz, __shfl_xor_sync(0xFFFFFFFFu, mnz, o2));
        mxz = fmaxf(mxz, __shfl_xor_sync(0xFFFFFFFFu, mxz, o2));
        mT  = fmaxf(mT,  __shfl_xor_sync(0xFFFFFFFFu, mT,  o2));
    }
    if (lane == 0) {
        int blk = g >> 5;
        g_blk[blk*2 + 0] = make_float4(mnx, mny, mnz, mT);
        g_blk[blk*2 + 1] = make_float4(mxx, mxy, mxz, 0.f);
    }
}

// ---------------------------------------------------------------------------
// K3: main. Warp = 64 Morton-adjacent points (2/lane, packed f32x2).
// blockIdx.y = 8-way split over gaussian blocks. For each of its 16 blocks the
// warp does ONE box-box test (point AABB vs block AABB, < maxT); inside a
// passing block, the per-gaussian packed test + ballot culls, then full eval.
// Superset-safe: |p-g|^2 < T  =>  boxdist^2 < maxT, so nonzero terms always
// evaluated; far terms are exactly +0.0.
// ---------------------------------------------------------------------------
__global__ void __launch_bounds__(128) main_kernel() {
    int warp = threadIdx.x >> 5;
    int lane = threadIdx.x & 31;
    int grp  = blockIdx.x * 4 + warp;
    int split = blockIdx.y;

    int s0 = grp*64 + 2*lane;
    int s1 = s0 + 1;
    float4 pa = g_spts[s0], pb = g_spts[s1];
    u64 npx = f2pack(pa.x, pb.x);
    u64 npy = f2pack(pa.y, pb.y);
    u64 npz = f2pack(pa.z, pb.z);

    // warp AABB of the (negated) points
    float mnx = fminf(pa.x, pb.x), mxx = fmaxf(pa.x, pb.x);
    float mny = fminf(pa.y, pb.y), mxy = fmaxf(pa.y, pb.y);
    float mnz = fminf(pa.z, pb.z), mxz = fmaxf(pa.z, pb.z);
#pragma unroll
    for (int o = 16; o; o >>= 1) {
        mnx = fminf(mnx, __shfl_xor_sync(0xFFFFFFFFu, mnx, o));
        mxx = fmaxf(mxx, __shfl_xor_sync(0xFFFFFFFFu, mxx, o));
        mny = fminf(mny, __shfl_xor_sync(0xFFFFFFFFu, mny, o));
        mxy = fmaxf(mxy, __shfl_xor_sync(0xFFFFFFFFu, mxy, o));
        mnz = fminf(mnz, __shfl_xor_sync(0xFFFFFFFFu, mnz, o));
        mxz = fmaxf(mxz, __shfl_xor_sync(0xFFFFFFFFu, mxz, o));
    }

    const u64 K3  = 0x4040000040400000ULL;  // { 3, 3}
    const u64 K5  = 0x40A0000040A00000ULL;  // { 5, 5}
    const u64 Kn2 = 0xC0000000C0000000ULL;  // {-2,-2}
    const u64 Kn3 = 0xC0400000C0400000ULL;  // {-3,-3}
    const u64 SGN = 0x8000000080000000ULL;

    u64 wacc = 0, ssacc = 0;

#pragma unroll 1
    for (int bi = 0; bi < BPS; ++bi) {
        int blk = split * BPS + bi;
        float4 b0 = __ldg(&g_blk[blk*2 + 0]);   // block min + maxT
        float4 b1 = __ldg(&g_blk[blk*2 + 1]);   // block max

        float dx = fmaxf(0.f, fmaxf(b0.x - mxx, mnx - b1.x));
        float dy = fmaxf(0.f, fmaxf(b0.y - mxy, mny - b1.y));
        float dz = fmaxf(0.f, fmaxf(b0.z - mxz, mnz - b1.z));
        if (fmaf(dx, dx, fmaf(dy, dy, dz*dz)) >= b0.w) continue;

        int gbase = blk * 32;
#pragma unroll 1
        for (int j = 0; j < 32; ++j) {
            const ulonglong2* G = &g_prm2[(gbase + j) * U2G];
            ulonglong2 q0 = __ldg(&G[0]), q1 = __ldg(&G[1]);

            u64 ex = f2add(q0.x, npx);   // e = gauss - point
            u64 ey = f2add(q0.y, npy);
            u64 ez = f2add(q1.x, npz);
            u64 exx = f2mul(ex, ex), eyy = f2mul(ey, ey), ezz = f2mul(ez, ez);
            u64 n2 = f2add(f2add(exx, eyy), ezz);

            float nA, nB; f2unpack(n2, nA, nB);
            float Tv, Tv2; f2unpack(q1.y, Tv, Tv2);
            bool act = (nA < Tv) || (nB < Tv);
            if (__ballot_sync(0xFFFFFFFFu, act)) {
                ulonglong2 q2 = __ldg(&G[2]), q3 = __ldg(&G[3]), q4 = __ldg(&G[4]);
                u64 pxy = f2mul(ex, ey), pxz = f2mul(ex, ez), pyz = f2mul(ey, ez);

                // exponent (pre-scaled by -0.5*log2e)
                u64 mm = f2mul(exx, q2.x);
                mm = f2fma(eyy, q2.y, mm);
                mm = f2fma(ezz, q3.x, mm);
                mm = f2fma(pxy, q3.y, mm);
                mm = f2fma(pxz, q4.x, mm);
                mm = f2fma(pyz, q4.y, mm);

                // aux polynomials in e
                u64 n2n  = n2 ^ SGN;
                u64 eyyn = eyy ^ SGN;
                u64 t6  = f2fma(K3, ezz, n2n);    // 3ezz - n2
                u64 uq  = f2add(exx, eyyn);       // exx - eyy
                u64 t9  = f2fma(K3, exx, eyyn);   // 3exx - eyy
                u64 w5  = f2fma(K5, ezz, n2n);    // 5ezz - n2
                u64 t12 = f2fma(Kn2, n2, w5);     // 5ezz - 3n2
                u64 t15 = f2fma(Kn3, ezz, uq);    // exx - eyy - 3ezz

                ulonglong2 q5 = __ldg(&G[5]), q6 = __ldg(&G[6]), q7 = __ldg(&G[7]);
                u64 S1 = f2fma(ex, q7.x, f2fma(ez, q6.y, f2mul(ey, q6.x)));
                ulonglong2 q8 = __ldg(&G[8]), q9 = __ldg(&G[9]);
                u64 S2 = f2fma(uq, q9.y,
                         f2fma(pxz, q9.x,
                         f2fma(t6, q8.y,
                         f2fma(pyz, q8.x, f2mul(pxy, q7.y)))));
                ulonglong2 q10 = __ldg(&G[10]), q11 = __ldg(&G[11]);
                ulonglong2 q12 = __ldg(&G[12]), q13 = __ldg(&G[13]);
                u64 m9  = f2mul(ey, t9);
                u64 m11 = f2mul(ey, w5);
                u64 m13 = f2mul(ex, w5);
                u64 m15 = f2mul(ex, t15);
                u64 S3a = f2mul(m9, q10.x);
                S3a = f2fma(m11, q11.x, S3a);
                S3a = f2fma(m13, q12.x, S3a);
                S3a = f2fma(m15, q13.x, S3a);
                u64 m10 = f2mul(pxy, ez);
                u64 m12 = f2mul(ez, t12);
                u64 m14 = f2mul(ez, uq);
                u64 S3b = f2mul(m10, q10.y);
                S3b = f2fma(m12, q11.y, S3b);
                S3b = f2fma(m14, q12.y, S3b);
                u64 S3 = f2add(S3a, S3b);

                // Horner in rinv: res = c0 + r*(S1 + r*(S2 + r*S3))
                u64 rq = f2pack(rsqf(nA), rsqf(nB));
                u64 res = f2fma(rq, S3, S2);
                res = f2fma(rq, res, S1);
                res = f2fma(rq, res, q5.y);

                float mA, mB; f2unpack(mm, mA, mB);
                u64 epk = f2pack(ex2f(mA), ex2f(mB));
                u64 w2 = f2mul(q5.x, epk);        // op * exp2(mm)
                wacc = f2add(wacc, w2);
                ssacc = f2fma(w2, f2relu(res), ssacc);
            }
        }
    }

    float wA, wB, sA, sB2;
    f2unpack(wacc, wA, wB);
    f2unpack(ssacc, sA, sB2);
    g_partial[(split*2 + 0)*N_PTS + s0] = wA;
    g_partial[(split*2 + 0)*N_PTS + s1] = wB;
    g_partial[(split*2 + 1)*N_PTS + s0] = sA;
    g_partial[(split*2 + 1)*N_PTS + s1] = sB2;
}

// ---------------------------------------------------------------------------
// K4: deterministic fixed-order reduction over splits + un-permute.
// ---------------------------------------------------------------------------
__global__ void reduce_kernel(float* __restrict__ out) {
    int slot = blockIdx.x * blockDim.x + threadIdx.x;
    if (slot >= N_PTS) return;
    float a = 0.f, b = 0.f;
#pragma unroll
    for (int s = 0; s < NSPLIT; ++s) {
        a += g_partial[(s*2 + 0) * N_PTS + slot];
        b += g_partial[(s*2 + 1) * N_PTS + slot];
    }
    int o = g_perm[slot];
    out[o] = a;
    out[N_PTS + o] = b;
}

extern "C" void kernel_launch(void* const* d_in, const int* in_sizes, int n_in,
                              void* d_out, int out_size) {
    const float* pts      = (const float*)d_in[0];  // network_pts
    // d_in[1] network_view, d_in[2] network_tx: unused by the reference math
    const float* xyz      = (const float*)d_in[3];
    const float* sh_dc    = (const float*)d_in[4];
    const float* sh_rest  = (const float*)d_in[5];
    const float* scaling  = (const float*)d_in[6];
    const float* rotation = (const float*)d_in[7];
    const float* opacity  = (const float*)d_in[8];

    sort_all_kernel<<<1, 1024>>>(pts, xyz);
    prep_kernel<<<N_GAUSS/128, 128>>>(xyz, sh_dc, sh_rest, scaling, rotation, opacity);
    main_kernel<<<dim3(NGRP/4, NSPLIT), 128>>>();
    reduce_kernel<<<(N_PTS + 255)/256, 256>>>((float*)d_out);
}

// round 17
// speedup vs baseline: 3.0029x; 2.7555x over previous
#include <cuda_runtime.h>

#define N_GAUSS 4096
#define N_PTS 32768
#define NSPLIT 8
#define GPS (N_GAUSS / NSPLIT)   /* 512 gaussians per split */
#define TILE 128
#define U2G 13                   /* ulonglong2 per gaussian (26 dup float2 slots) */
#define NCELL 4096               /* 16^3 Morton grid, cell 0.5 over [-4,4] */

typedef unsigned long long u64;

__device__ ulonglong2 g_prm2[N_GAUSS * U2G];   // dup params for f32x2 eval
__device__ float4 g_tst[N_GAUSS];              // {gx,gy,gz,sqrtT} test array
__device__ float  g_partial[NSPLIT * 2 * N_PTS];
__device__ int    g_cnt[NCELL];                // zero-init; scan re-zeros each call
__device__ int    g_cur[NCELL];
__device__ int    g_cid[N_PTS];
__device__ int    g_perm[N_PTS];
__device__ float4 g_spts[N_PTS];               // sorted NEGATED points

__device__ __forceinline__ float ex2f(float x) {
    float y; asm("ex2.approx.ftz.f32 %0, %1;" : "=f"(y) : "f"(x)); return y;
}
__device__ __forceinline__ float rsqf(float x) {
    float y; asm("rsqrt.approx.ftz.f32 %0, %1;" : "=f"(y) : "f"(x)); return y;
}
__device__ __forceinline__ u64 f2fma(u64 a, u64 b, u64 c) {
    u64 d; asm("fma.rn.f32x2 %0, %1, %2, %3;" : "=l"(d) : "l"(a), "l"(b), "l"(c)); return d;
}
__device__ __forceinline__ u64 f2mul(u64 a, u64 b) {
    u64 d; asm("mul.rn.f32x2 %0, %1, %2;" : "=l"(d) : "l"(a), "l"(b)); return d;
}
__device__ __forceinline__ u64 f2add(u64 a, u64 b) {
    u64 d; asm("add.rn.f32x2 %0, %1, %2;" : "=l"(d) : "l"(a), "l"(b)); return d;
}
__device__ __forceinline__ u64 f2pack(float lo, float hi) {
    u64 d; asm("mov.b64 %0, {%1, %2};" : "=l"(d) : "f"(lo), "f"(hi)); return d;
}
__device__ __forceinline__ void f2unpack(u64 v, float& lo, float& hi) {
    asm("mov.b64 {%0, %1}, %2;" : "=f"(lo), "=f"(hi) : "l"(v));
}
__device__ __forceinline__ u64 f2relu(u64 v) {
    unsigned lo = (unsigned)v, hi = (unsigned)(v >> 32);
    lo &= ~(unsigned)(((int)lo) >> 31);
    hi &= ~(unsigned)(((int)hi) >> 31);
    return ((u64)hi << 32) | lo;
}
__device__ __forceinline__ int cellof(float v) {
    return min(15, max(0, (int)floorf((v + 4.f) * 2.f)));
}
__device__ __forceinline__ int mort3(int ix, int iy, int iz) {
    int c = 0;
#pragma unroll
    for (int b = 0; b < 4; ++b)
        c |= (((ix >> b) & 1) << (3*b)) | (((iy >> b) & 1) << (3*b + 1))
           | (((iz >> b) & 1) << (3*b + 2));
    return c;
}

// ---------------------------------------------------------------------------
// K1 (fused): blocks 0..15 = per-gaussian prep, blocks 16..143 = point Morton
// cell-count. Independent work, one launch.
// Prep layout (26 dup float2 slots = 13 ull2):
//  q0:{gx,gy} q1:{gz,P0} q2:{P1,P2} q3:{P3,P4} q4:{P5,op}
//  q5:{c0,c1} q6:{c2,c3} q7:{c4,c5} q8:{c6,c7} q9:{c8,c9}
//  q10:{c10,c11} q11:{c12,c13} q12:{c14,c15}
// P* pre-scaled by -0.5*log2(e), off-diagonals doubled.
// T = 230*smax^2: n2 >= T  =>  exp(-0.5*maha) == +0.0f exactly (reference too)
// -> lossless cull; g_tst stores sqrt(T).
// ---------------------------------------------------------------------------
__global__ void __launch_bounds__(256) prep_count_kernel(
                            const float* __restrict__ pts,
                            const float* __restrict__ xyz,
                            const float* __restrict__ sh_dc,
                            const float* __restrict__ sh_rest,
                            const float* __restrict__ scaling,
                            const float* __restrict__ rotation,
                            const float* __restrict__ opacity) {
    if (blockIdx.x >= 16) {
        // ---- point counting (Morton cells) ----
        int i = (blockIdx.x - 16) * 256 + threadIdx.x;
        int c = mort3(cellof(pts[i*3+0]), cellof(pts[i*3+1]), cellof(pts[i*3+2]));
        g_cid[i] = c;
        atomicAdd(&g_cnt[c], 1);
        return;
    }

    int g = blockIdx.x * 256 + threadIdx.x;

    float qr = rotation[g*4+0], qx = rotation[g*4+1];
    float qy = rotation[g*4+2], qz = rotation[g*4+3];
    float qn = rsqrtf(qr*qr + qx*qx + qy*qy + qz*qz);
    qr *= qn; qx *= qn; qy *= qn; qz *= qn;

    float R00 = 1.f - 2.f*(qy*qy + qz*qz), R01 = 2.f*(qx*qy - qr*qz), R02 = 2.f*(qx*qz + qr*qy);
    float R10 = 2.f*(qx*qy + qr*qz), R11 = 1.f - 2.f*(qx*qx + qz*qz), R12 = 2.f*(qy*qz - qr*qx);
    float R20 = 2.f*(qx*qz - qr*qy), R21 = 2.f*(qy*qz + qr*qx), R22 = 1.f - 2.f*(qx*qx + qy*qy);

    float s0 = expf(scaling[g*3+0]);
    float s1 = expf(scaling[g*3+1]);
    float s2 = expf(scaling[g*3+2]);
    float iv0 = 1.f/(s0*s0), iv1 = 1.f/(s1*s1), iv2 = 1.f/(s2*s2);
    float smax = fmaxf(s0, fmaxf(s1, s2));
    float T = 230.f * smax * smax;

    float Pxx = iv0*R00*R00 + iv1*R01*R01 + iv2*R02*R02;
    float Pyy = iv0*R10*R10 + iv1*R11*R11 + iv2*R12*R12;
    float Pzz = iv0*R20*R20 + iv1*R21*R21 + iv2*R22*R22;
    float Pxy = iv0*R00*R10 + iv1*R01*R11 + iv2*R02*R12;
    float Pxz = iv0*R00*R20 + iv1*R01*R21 + iv2*R02*R22;
    float Pyz = iv0*R10*R20 + iv1*R11*R21 + iv2*R12*R22;

    const float kk = -0.7213475204444817f;  // -0.5 * log2(e)
    float op = 1.f / (1.f + expf(-opacity[g]));

    const float C0 = 0.28209479177387814f;
    const float C1 = 0.4886025119029199f;
    const float* sr = sh_rest + g*15;
    float c[16];
    c[0]  =  C0 * sh_dc[g];
    c[1]  = -C1 * sr[0];
    c[2]  =  C1 * sr[1];
    c[3]  = -C1 * sr[2];
    c[4]  =  1.0925484305920792f  * sr[3];
    c[5]  = -1.0925484305920792f  * sr[4];
    c[6]  =  0.31539156525252005f * sr[5];
    c[7]  = -1.0925484305920792f  * sr[6];
    c[8]  =  0.5462742152960396f  * sr[7];
    c[9]  = -0.5900435899266435f  * sr[8];
    c[10] =  2.890611442640554f   * sr[9];
    c[11] = -0.4570457994644658f  * sr[10];
    c[12] =  0.3731763325901154f  * sr[11];
    c[13] = -0.4570457994644658f  * sr[12];
    c[14] =  1.445305721320277f   * sr[13];
    c[15] = -0.5900435899266435f  * sr[14];

    float gx = xyz[g*3+0], gy = xyz[g*3+1], gz = xyz[g*3+2];
    g_tst[g] = make_float4(gx, gy, gz, sqrtf(T));

    float v[26];
    v[0] = gx; v[1] = gy; v[2] = gz;
    v[3] = kk*Pxx; v[4] = kk*Pyy; v[5] = kk*Pzz;
    v[6] = 2.f*kk*Pxy; v[7] = 2.f*kk*Pxz; v[8] = 2.f*kk*Pyz;
    v[9] = op;
#pragma unroll
    for (int i = 0; i < 16; ++i) v[10+i] = c[i];

    float2* o = (float2*)&g_prm2[g * U2G];
#pragma unroll
    for (int i = 0; i < 26; ++i) o[i] = make_float2(v[i], v[i]);
}

// ---------------------------------------------------------------------------
// K2: exclusive scan over 4096 cells + re-zero g_cnt for the next replay.
// ---------------------------------------------------------------------------
__global__ void __launch_bounds__(1024) scan_kernel() {
    __shared__ int ps[1024];
    int t = threadIdx.x;
    int l0 = g_cnt[t*4+0], l1 = g_cnt[t*4+1], l2 = g_cnt[t*4+2], l3 = g_cnt[t*4+3];
    g_cnt[t*4+0] = 0; g_cnt[t*4+1] = 0; g_cnt[t*4+2] = 0; g_cnt[t*4+3] = 0;
    int s = l0 + l1 + l2 + l3;
    ps[t] = s; __syncthreads();
    for (int off = 1; off < 1024; off <<= 1) {
        int v = (t >= off) ? ps[t - off] : 0;
        __syncthreads();
        ps[t] += v;
        __syncthreads();
    }
    int run = ps[t] - s;
    g_cur[t*4+0] = run; run += l0;
    g_cur[t*4+1] = run; run += l1;
    g_cur[t*4+2] = run; run += l2;
    g_cur[t*4+3] = run;
}

// ---------------------------------------------------------------------------
// K3: scatter into Morton-sorted order (negated coords).
// Within-cell order from atomics is nondeterministic but provably harmless:
// every gaussian's term for a point is either evaluated (identical math on
// whichever lane holds the point, fixed ascending gaussian order) or is
// exactly +0.0 when skipped/included-far; accumulators never hold -0.0.
// ---------------------------------------------------------------------------
__global__ void scatter_kernel(const float* __restrict__ pts) {
    int i = blockIdx.x * blockDim.x + threadIdx.x;
    if (i >= N_PTS) return;
    int slot = atomicAdd(&g_cur[g_cid[i]], 1);
    g_perm[slot] = i;
    g_spts[slot] = make_float4(-pts[i*3+0], -pts[i*3+1], -pts[i*3+2], 0.f);
}

// ---------------------------------------------------------------------------
// K4: main. Warp = 64 Morton-adjacent points (2/lane, packed f32x2).
// blockIdx.y = 8-way gaussian split; per split, 4 tiles of 128 gaussians
// staged through SMEM (test float4 + 13 ull2 params).
// Uniform cull: scalar midpoint test |mid-g| < sqrtT + h (superset of the
// exact 2-point test by triangle inequality). On warp-pass: evaluate both
// points unconditionally — far points give ex2f(m<=-166) == +0.0 exactly.
// ---------------------------------------------------------------------------
__global__ void __launch_bounds__(128) main_kernel() {
    int tid = threadIdx.x;
    int lane = tid & 31;
    int grp = blockIdx.x * 4 + (tid >> 5);
    int split = blockIdx.y;

    int s0 = grp*64 + 2*lane;
    int s1 = s0 + 1;
    float4 pa = g_spts[s0], pb = g_spts[s1];          // negated points
    u64 npx = f2pack(pa.x, pb.x);
    u64 npy = f2pack(pa.y, pb.y);
    u64 npz = f2pack(pa.z, pb.z);
    // pair midpoint (negated space) + half-distance
    float nmx = 0.5f*(pa.x + pb.x);
    float nmy = 0.5f*(pa.y + pb.y);
    float nmz = 0.5f*(pa.z + pb.z);
    float hx = pa.x - pb.x, hy = pa.y - pb.y, hz = pa.z - pb.z;
    float h = 0.5f * sqrtf(hx*hx + hy*hy + hz*hz);

    const u64 K3  = 0x4040000040400000ULL;  // { 3, 3}
    const u64 K5  = 0x40A0000040A00000ULL;  // { 5, 5}
    const u64 Kn2 = 0xC0000000C0000000ULL;  // {-2,-2}
    const u64 Kn3 = 0xC0400000C0400000ULL;  // {-3,-3}
    const u64 SGN = 0x8000000080000000ULL;

    __shared__ float4 stst[TILE];
    __shared__ ulonglong2 sprm[TILE * U2G];

    u64 wacc = 0, ssacc = 0;
    int gbase = split * GPS;

    for (int t = 0; t < GPS; t += TILE) {
        __syncthreads();
        const float4* ts = &g_tst[gbase + t];
        for (int i = tid; i < TILE; i += 128) stst[i] = ts[i];
        const ulonglong2* src = &g_prm2[(gbase + t) * U2G];
        for (int i = tid; i < TILE * U2G; i += 128) sprm[i] = src[i];
        __syncthreads();

#pragma unroll 4
        for (int j = 0; j < TILE; ++j) {
            float4 gt = stst[j];
            // scalar midpoint test (gt.xyz = +center; nm = negated midpoint)
            float dx = gt.x + nmx, dy = gt.y + nmy, dz = gt.z + nmz;
            float d2 = fmaf(dx, dx, fmaf(dy, dy, dz*dz));
            float thr = gt.w + h;
            bool act = d2 < thr*thr;
            if (!__ballot_sync(0xFFFFFFFFu, act)) continue;

            const ulonglong2* G = &sprm[j * U2G];
            ulonglong2 q0 = G[0], q1 = G[1], q2 = G[2], q3 = G[3], q4 = G[4];

            u64 ex = f2add(q0.x, npx);   // e = gauss - point
            u64 ey = f2add(q0.y, npy);
            u64 ez = f2add(q1.x, npz);
            u64 exx = f2mul(ex, ex), eyy = f2mul(ey, ey), ezz = f2mul(ez, ez);
            u64 n2 = f2add(f2add(exx, eyy), ezz);
            u64 pxy = f2mul(ex, ey), pxz = f2mul(ex, ez), pyz = f2mul(ey, ez);

            // exponent (pre-scaled by -0.5*log2e); far points -> exactly +0
            u64 mm = f2mul(exx, q1.y);
            mm = f2fma(eyy, q2.x, mm);
            mm = f2fma(ezz, q2.y, mm);
            mm = f2fma(pxy, q3.x, mm);
            mm = f2fma(pxz, q3.y, mm);
            mm = f2fma(pyz, q4.x, mm);

            // aux polynomials in e
            u64 n2n  = n2 ^ SGN;
            u64 eyyn = eyy ^ SGN;
            u64 t6  = f2fma(K3, ezz, n2n);    // 3ezz - n2
            u64 uq  = f2add(exx, eyyn);       // exx - eyy
            u64 t9  = f2fma(K3, exx, eyyn);   // 3exx - eyy
            u64 w5  = f2fma(K5, ezz, n2n);    // 5ezz - n2
            u64 t12 = f2fma(Kn2, n2, w5);     // 5ezz - 3n2
            u64 t15 = f2fma(Kn3, ezz, uq);    // exx - eyy - 3ezz

            ulonglong2 q5 = G[5], q6 = G[6], q7 = G[7];
            u64 S1 = f2fma(ex, q6.y, f2fma(ez, q6.x, f2mul(ey, q5.y)));
            ulonglong2 q8 = G[8], q9 = G[9];
            u64 S2 = f2fma(uq, q9.x,
                     f2fma(pxz, q8.y,
                     f2fma(t6, q8.x,
                     f2fma(pyz, q7.y, f2mul(pxy, q7.x)))));
            ulonglong2 q10 = G[10], q11 = G[11], q12 = G[12];
            u64 m9  = f2mul(ey, t9);
            u64 m11 = f2mul(ey, w5);
            u64 m13 = f2mul(ex, w5);
            u64 m15 = f2mul(ex, t15);
            u64 S3a = f2mul(m9, q9.y);
            S3a = f2fma(m11, q10.y, S3a);
            S3a = f2fma(m13, q11.y, S3a);
            S3a = f2fma(m15, q12.y, S3a);
            u64 m10 = f2mul(pxy, ez);
            u64 m12 = f2mul(ez, t12);
            u64 m14 = f2mul(ez, uq);
            u64 S3b = f2mul(m10, q10.x);
            S3b = f2fma(m12, q11.x, S3b);
            S3b = f2fma(m14, q12.x, S3b);
            u64 S3 = f2add(S3a, S3b);

            // Horner in rinv: res = c0 + r*(S1 + r*(S2 + r*S3))
            float nA, nB; f2unpack(n2, nA, nB);
            u64 rq = f2pack(rsqf(nA), rsqf(nB));
            u64 res = f2fma(rq, S3, S2);
            res = f2fma(rq, res, S1);
            res = f2fma(rq, res, q5.x);

            float mA, mB; f2unpack(mm, mA, mB);
            u64 epk = f2pack(ex2f(mA), ex2f(mB));
            u64 w2 = f2mul(q4.y, epk);        // op * exp2(mm)
            wacc = f2add(wacc, w2);
            ssacc = f2fma(w2, f2relu(res), ssacc);
        }
    }

    float wA, wB, sA, sB2;
    f2unpack(wacc, wA, wB);
    f2unpack(ssacc, sA, sB2);
    g_partial[(split*2 + 0)*N_PTS + s0] = wA;
    g_partial[(split*2 + 0)*N_PTS + s1] = wB;
    g_partial[(split*2 + 1)*N_PTS + s0] = sA;
    g_partial[(split*2 + 1)*N_PTS + s1] = sB2;
}

// ---------------------------------------------------------------------------
// K5: deterministic fixed-order reduction over splits + un-permute.
// ---------------------------------------------------------------------------
__global__ void reduce_kernel(float* __restrict__ out) {
    int slot = blockIdx.x * blockDim.x + threadIdx.x;
    if (slot >= N_PTS) return;
    float a = 0.f, b = 0.f;
#pragma unroll
    for (int s = 0; s < NSPLIT; ++s) {
        a += g_partial[(s*2 + 0) * N_PTS + slot];
        b += g_partial[(s*2 + 1) * N_PTS + slot];
    }
    int o = g_perm[slot];
    out[o] = a;
    out[N_PTS + o] = b;
}

extern "C" void kernel_launch(void* const* d_in, const int* in_sizes, int n_in,
                              void* d_out, int out_size) {
    const float* pts      = (const float*)d_in[0];  // network_pts
    // d_in[1] network_view, d_in[2] network_tx: unused by the reference math
    const float* xyz      = (const float*)d_in[3];
    const float* sh_dc    = (const float*)d_in[4];
    const float* sh_rest  = (const float*)d_in[5];
    const float* scaling  = (const float*)d_in[6];
    const float* rotation = (const float*)d_in[7];
    const float* opacity  = (const float*)d_in[8];

    prep_count_kernel<<<16 + N_PTS/256, 256>>>(pts, xyz, sh_dc, sh_rest,
                                               scaling, rotation, opacity);
    scan_kernel<<<1, 1024>>>();
    scatter_kernel<<<N_PTS/256, 256>>>(pts);
    main_kernel<<<dim3(N_PTS/64/4, NSPLIT), 128>>>();   // 512 groups / 4 warps = 128 CTAs
    reduce_kernel<<<(N_PTS + 255)/256, 256>>>((float*)d_out);
}